// round 12
// baseline (speedup 1.0000x reference)
#include <cuda_runtime.h>
#include <cuda_bf16.h>
#include <cuda_fp16.h>
#include <cstdint>

#define N_NODES  50000
#define N_EDGES  800000
#define HID      128
#define N_GRAPHS 512

// ---------------- scratch ----------------
__device__ int   g_deg[N_NODES];
__device__ int   g_tmp_incl[N_NODES];
__device__ int   g_bsum[64];
__device__ int   g_cursor[N_NODES];
__device__ int   g_row_start[N_NODES + 1];
__device__ int   g_counts[N_GRAPHS];
__device__ int   g_csr_src[N_EDGES];
__device__ float g_inv_deg[N_NODES];

// double-buffered layer products
__device__ __half g_ylhA[(size_t)N_NODES * 128];
__device__ float  g_yrA[(size_t)N_NODES * 128];
__device__ __half g_ylhB[(size_t)N_NODES * 128];
__device__ float  g_yrB[(size_t)N_NODES * 128];

// converted weights: [layer][256 rows (Wl then Wr)][128 k]
__device__ __nv_bfloat16 g_whi[3 * 256 * 128];
__device__ __nv_bfloat16 g_wlo[3 * 256 * 128];

// ---------------- split helpers ----------------
__device__ __forceinline__ void split1(float v, __nv_bfloat16& hi, __nv_bfloat16& lo) {
    hi = __float2bfloat16_rn(v);
    lo = __float2bfloat16_rn(v - __bfloat162float(hi));
}
__device__ __forceinline__ void split_pack4(float4 v, uint2& hi, uint2& lo) {
    __nv_bfloat16 hx, hy, hz, hw, lx, ly, lz, lw;
    split1(v.x, hx, lx); split1(v.y, hy, ly); split1(v.z, hz, lz); split1(v.w, hw, lw);
    hi.x = ((uint32_t)__bfloat16_as_ushort(hy) << 16) | __bfloat16_as_ushort(hx);
    hi.y = ((uint32_t)__bfloat16_as_ushort(hw) << 16) | __bfloat16_as_ushort(hz);
    lo.x = ((uint32_t)__bfloat16_as_ushort(ly) << 16) | __bfloat16_as_ushort(lx);
    lo.y = ((uint32_t)__bfloat16_as_ushort(lw) << 16) | __bfloat16_as_ushort(lz);
}

// ---------------- init: zero deg/counts/pooled + convert weights ----------------
__global__ void init_kernel(float* __restrict__ pooled,
                            const float* __restrict__ W1l, const float* __restrict__ W1r,
                            const float* __restrict__ W2l, const float* __restrict__ W2r,
                            const float* __restrict__ W3l, const float* __restrict__ W3r) {
    int i = blockIdx.x * blockDim.x + threadIdx.x;
    int stride = gridDim.x * blockDim.x;
    for (int j = i; j < N_NODES; j += stride) g_deg[j] = 0;
    for (int j = i; j < N_GRAPHS; j += stride) g_counts[j] = 0;
    for (int j = i; j < N_GRAPHS * HID; j += stride) pooled[j] = 0.0f;
    for (int idx = i; idx < 3 * 256 * 128; idx += stride) {
        int layer = idx / (256 * 128);
        int rem = idx % (256 * 128);
        int n = rem / 128, k = rem % 128;
        const float* Wp;
        if (layer == 0) Wp = (n < 128) ? W1l : W1r;
        else if (layer == 1) Wp = (n < 128) ? W2l : W2r;
        else Wp = (n < 128) ? W3l : W3r;
        float v = Wp[(n & 127) * 128 + k];
        __nv_bfloat16 hi, lo;
        split1(v, hi, lo);
        g_whi[idx] = hi;
        g_wlo[idx] = lo;
    }
}

// ---------------- histograms: 4 edges/thread (int4) ----------------
__global__ void hist_kernel(const int* __restrict__ ei, const int* __restrict__ batch) {
    int q = blockIdx.x * blockDim.x + threadIdx.x;
    if (q < N_EDGES / 4) {
        int4 d = *reinterpret_cast<const int4*>(&ei[N_EDGES + q * 4]);
        atomicAdd(&g_deg[d.x], 1);
        atomicAdd(&g_deg[d.y], 1);
        atomicAdd(&g_deg[d.z], 1);
        atomicAdd(&g_deg[d.w], 1);
    }
    if (q < N_NODES / 4) {
        int4 b = *reinterpret_cast<const int4*>(&batch[q * 4]);
        atomicAdd(&g_counts[b.x], 1);
        atomicAdd(&g_counts[b.y], 1);
        atomicAdd(&g_counts[b.z], 1);
        atomicAdd(&g_counts[b.w], 1);
    }
}

// ---------------- scan A: per-block inclusive scans of deg ----------------
__global__ __launch_bounds__(1024)
void scanA_kernel() {
    __shared__ int wsum[32];
    const int t = threadIdx.x, lane = t & 31, wid = t >> 5;
    const int i = blockIdx.x * 1024 + t;
    int v = (i < N_NODES) ? g_deg[i] : 0;
    int x = v;
#pragma unroll
    for (int o = 1; o < 32; o <<= 1) {
        int y = __shfl_up_sync(0xffffffffu, x, o);
        if (lane >= o) x += y;
    }
    if (lane == 31) wsum[wid] = x;
    __syncthreads();
    if (wid == 0) {
        int w = wsum[lane];
#pragma unroll
        for (int o = 1; o < 32; o <<= 1) {
            int y = __shfl_up_sync(0xffffffffu, w, o);
            if (lane >= o) w += y;
        }
        wsum[lane] = w;
    }
    __syncthreads();
    int incl = x + (wid ? wsum[wid - 1] : 0);
    if (i < N_NODES) g_tmp_incl[i] = incl;
    if (t == 1023) g_bsum[blockIdx.x] = incl;
}

// ---------------- scan C: redundant 64-wide block-sum scan + finalize ----------------
__global__ __launch_bounds__(1024)
void scanC_kernel(int nblocks) {
    __shared__ int s[64];
    const int t = threadIdx.x;
    if (t < 64) s[t] = (t < nblocks) ? g_bsum[t] : 0;
    __syncthreads();
#pragma unroll
    for (int o = 1; o < 64; o <<= 1) {
        int v = 0;
        if (t < 64 && t >= o) v = s[t - o];
        __syncthreads();
        if (t < 64) s[t] += v;
        __syncthreads();
    }
    const int i = blockIdx.x * 1024 + t;
    if (i >= N_NODES) return;
    int boff = blockIdx.x ? s[blockIdx.x - 1] : 0;
    int d = g_deg[i];
    int rs = boff + g_tmp_incl[i] - d;
    g_row_start[i] = rs;
    g_cursor[i]    = rs;
    g_inv_deg[i]   = 1.0f / fmaxf((float)d, 1.0f);
    if (i == N_NODES - 1) g_row_start[N_NODES] = rs + d;
}

// ---------------- CSR fill: 4 edges/thread (int4) ----------------
__global__ void csr_kernel(const int* __restrict__ ei) {
    int q = blockIdx.x * blockDim.x + threadIdx.x;
    if (q >= N_EDGES / 4) return;
    int4 s = *reinterpret_cast<const int4*>(&ei[q * 4]);
    int4 d = *reinterpret_cast<const int4*>(&ei[N_EDGES + q * 4]);
    int p0 = atomicAdd(&g_cursor[d.x], 1);
    int p1 = atomicAdd(&g_cursor[d.y], 1);
    int p2 = atomicAdd(&g_cursor[d.z], 1);
    int p3 = atomicAdd(&g_cursor[d.w], 1);
    g_csr_src[p0] = s.x;
    g_csr_src[p1] = s.y;
    g_csr_src[p2] = s.z;
    g_csr_src[p3] = s.w;
}

// ---------------- fp16 gather helper ----------------
__device__ __forceinline__ void acc_half4(float4& acc, const __half* p) {
    uint2 u = *reinterpret_cast<const uint2*>(p);
    float2 f0 = __half22float2(*reinterpret_cast<__half2*>(&u.x));
    float2 f1 = __half22float2(*reinterpret_cast<__half2*>(&u.y));
    acc.x += f0.x; acc.y += f0.y; acc.z += f1.x; acc.w += f1.y;
}

// ---------------- mma.sync bf16 GEMM with (optionally) fused combine staging ----------------
// MODE 0: A tile staged from fp32 X (bf16 hi/lo split in staging)
// MODE 1: A tile = combine(prev layer) computed in staging:
//         h[i] = relu(inv_deg[i]*sum ylh_in[src] + yr_in[i] + bias), split to hi/lo smem
// bf16x2 split mma: D = Ahi@Bhi + Ahi@Blo + Alo@Bhi (fp32 accum)
#define ASTR 136                       // smem row stride in bf16 elems (conflict-free)
static const int SM_AHI = 0;
static const int SM_ALO = SM_AHI + 128 * ASTR * 2;   // 34816
static const int SM_BHI = SM_ALO + 128 * ASTR * 2;   // 69632
static const int SM_BLO = SM_BHI + 256 * ASTR * 2;   // 139264
static const int SM_TOT = SM_BLO + 256 * ASTR * 2;   // 208896

__device__ __forceinline__ void mma16816(float* c, const uint32_t* a, const uint32_t* b) {
    asm volatile(
        "mma.sync.aligned.m16n8k16.row.col.f32.bf16.bf16.f32 "
        "{%0,%1,%2,%3}, {%4,%5,%6,%7}, {%8,%9}, {%0,%1,%2,%3};"
        : "+f"(c[0]), "+f"(c[1]), "+f"(c[2]), "+f"(c[3])
        : "r"(a[0]), "r"(a[1]), "r"(a[2]), "r"(a[3]), "r"(b[0]), "r"(b[1]));
}

template <int MODE>
__global__ __launch_bounds__(256, 1)
void gemm_tc_kernel(const float* __restrict__ X,
                    const __half* __restrict__ ylh_in, const float* __restrict__ yr_in,
                    const float* __restrict__ bias,
                    const __nv_bfloat16* __restrict__ Whi, const __nv_bfloat16* __restrict__ Wlo,
                    __half* __restrict__ ylh_out, float* __restrict__ yr_out) {
    extern __shared__ char smem[];
    const int t = threadIdx.x;
    const int row0 = blockIdx.x * 128;
    const int wid = t >> 5, lane = t & 31;

    if (MODE == 0) {
        // ---- stage A from fp32 X: split during staging ----
#pragma unroll
        for (int i = t; i < 128 * 32; i += 256) {
            int r = i >> 5, k = (i & 31) * 4;
            int row = row0 + r;
            float4 v = make_float4(0.f, 0.f, 0.f, 0.f);
            if (row < N_NODES) v = *reinterpret_cast<const float4*>(&X[(size_t)row * HID + k]);
            uint2 hi, lo;
            split_pack4(v, hi, lo);
            *reinterpret_cast<uint2*>(smem + SM_AHI + (r * ASTR + k) * 2) = hi;
            *reinterpret_cast<uint2*>(smem + SM_ALO + (r * ASTR + k) * 2) = lo;
        }
    } else {
        // ---- stage A = fused combine of previous layer (warp per node, 8-deep gather) ----
        const int lo4 = lane * 4;
        for (int nn = wid; nn < 128; nn += 8) {
            int i = row0 + nn;
            float4 r4 = make_float4(0.f, 0.f, 0.f, 0.f);
            if (i < N_NODES) {
                int e0 = g_row_start[i], e1 = g_row_start[i + 1];
                float4 A0 = make_float4(0, 0, 0, 0), A1 = A0, A2 = A0, A3 = A0;
                float4 A4 = A0, A5 = A0, A6 = A0, A7 = A0;
                for (int base = e0; base < e1; base += 8) {
                    // 8 independent predicated gather chains (keeps MLP high)
                    if (base + 0 < e1) acc_half4(A0, &ylh_in[(size_t)g_csr_src[base + 0] * 128 + lo4]);
                    if (base + 1 < e1) acc_half4(A1, &ylh_in[(size_t)g_csr_src[base + 1] * 128 + lo4]);
                    if (base + 2 < e1) acc_half4(A2, &ylh_in[(size_t)g_csr_src[base + 2] * 128 + lo4]);
                    if (base + 3 < e1) acc_half4(A3, &ylh_in[(size_t)g_csr_src[base + 3] * 128 + lo4]);
                    if (base + 4 < e1) acc_half4(A4, &ylh_in[(size_t)g_csr_src[base + 4] * 128 + lo4]);
                    if (base + 5 < e1) acc_half4(A5, &ylh_in[(size_t)g_csr_src[base + 5] * 128 + lo4]);
                    if (base + 6 < e1) acc_half4(A6, &ylh_in[(size_t)g_csr_src[base + 6] * 128 + lo4]);
                    if (base + 7 < e1) acc_half4(A7, &ylh_in[(size_t)g_csr_src[base + 7] * 128 + lo4]);
                }
                float sx = ((A0.x + A1.x) + (A2.x + A3.x)) + ((A4.x + A5.x) + (A6.x + A7.x));
                float sy = ((A0.y + A1.y) + (A2.y + A3.y)) + ((A4.y + A5.y) + (A6.y + A7.y));
                float sz = ((A0.z + A1.z) + (A2.z + A3.z)) + ((A4.z + A5.z) + (A6.z + A7.z));
                float sw = ((A0.w + A1.w) + (A2.w + A3.w)) + ((A4.w + A5.w) + (A6.w + A7.w));
                float inv = g_inv_deg[i];
                float4 yr = *reinterpret_cast<const float4*>(&yr_in[(size_t)i * 128 + lo4]);
                float4 bb = *reinterpret_cast<const float4*>(&bias[lo4]);
                r4.x = fmaxf(fmaf(sx, inv, yr.x + bb.x), 0.0f);
                r4.y = fmaxf(fmaf(sy, inv, yr.y + bb.y), 0.0f);
                r4.z = fmaxf(fmaf(sz, inv, yr.z + bb.z), 0.0f);
                r4.w = fmaxf(fmaf(sw, inv, yr.w + bb.w), 0.0f);
            }
            uint2 hi, lo;
            split_pack4(r4, hi, lo);
            *reinterpret_cast<uint2*>(smem + SM_AHI + (nn * ASTR + lo4) * 2) = hi;
            *reinterpret_cast<uint2*>(smem + SM_ALO + (nn * ASTR + lo4) * 2) = lo;
        }
    }

    // ---- stage B (256x128 bf16 hi/lo, preconverted) ----
#pragma unroll
    for (int i = t; i < 256 * 16; i += 256) {
        int n = i >> 4, k = (i & 15) * 8;
        *reinterpret_cast<uint4*>(smem + SM_BHI + (n * ASTR + k) * 2) =
            *reinterpret_cast<const uint4*>(&Whi[n * HID + k]);
        *reinterpret_cast<uint4*>(smem + SM_BLO + (n * ASTR + k) * 2) =
            *reinterpret_cast<const uint4*>(&Wlo[n * HID + k]);
    }
    __syncthreads();

    const int g = lane >> 2, tig = lane & 3;
    const int wm = (wid & 1) * 64;        // warp M offset (2 warps in M)
    const int wn = (wid >> 1) * 64;       // warp N offset (4 warps in N)

    float acc[4][8][4];
#pragma unroll
    for (int a = 0; a < 4; a++)
#pragma unroll
        for (int b = 0; b < 8; b++)
#pragma unroll
            for (int c = 0; c < 4; c++) acc[a][b][c] = 0.0f;

    for (int ks = 0; ks < 8; ks++) {
        const int k0 = ks * 16 + tig * 2;
        uint32_t ah[4][4], al[4][4];
#pragma unroll
        for (int mt = 0; mt < 4; mt++) {
            int base = ((wm + mt * 16 + g) * ASTR + k0) * 2;
            ah[mt][0] = *reinterpret_cast<const uint32_t*>(smem + SM_AHI + base);
            ah[mt][1] = *reinterpret_cast<const uint32_t*>(smem + SM_AHI + base + 8 * ASTR * 2);
            ah[mt][2] = *reinterpret_cast<const uint32_t*>(smem + SM_AHI + base + 16);
            ah[mt][3] = *reinterpret_cast<const uint32_t*>(smem + SM_AHI + base + 8 * ASTR * 2 + 16);
            al[mt][0] = *reinterpret_cast<const uint32_t*>(smem + SM_ALO + base);
            al[mt][1] = *reinterpret_cast<const uint32_t*>(smem + SM_ALO + base + 8 * ASTR * 2);
            al[mt][2] = *reinterpret_cast<const uint32_t*>(smem + SM_ALO + base + 16);
            al[mt][3] = *reinterpret_cast<const uint32_t*>(smem + SM_ALO + base + 8 * ASTR * 2 + 16);
        }
#pragma unroll
        for (int nh = 0; nh < 2; nh++) {
            uint32_t bh[4][2], bl[4][2];
#pragma unroll
            for (int nt = 0; nt < 4; nt++) {
                int base = ((wn + nh * 32 + nt * 8 + g) * ASTR + k0) * 2;
                bh[nt][0] = *reinterpret_cast<const uint32_t*>(smem + SM_BHI + base);
                bh[nt][1] = *reinterpret_cast<const uint32_t*>(smem + SM_BHI + base + 16);
                bl[nt][0] = *reinterpret_cast<const uint32_t*>(smem + SM_BLO + base);
                bl[nt][1] = *reinterpret_cast<const uint32_t*>(smem + SM_BLO + base + 16);
            }
#pragma unroll
            for (int mt = 0; mt < 4; mt++)
#pragma unroll
                for (int nt = 0; nt < 4; nt++) {
                    float* c = acc[mt][nh * 4 + nt];
                    mma16816(c, ah[mt], bh[nt]);
                    mma16816(c, ah[mt], bl[nt]);
                    mma16816(c, al[mt], bh[nt]);
                }
        }
    }

    // ---- epilogue: cols [0,128) -> fp16 ylh_out ; cols [128,256) -> fp32 yr_out ----
#pragma unroll
    for (int mt = 0; mt < 4; mt++)
#pragma unroll
        for (int nt = 0; nt < 8; nt++) {
            int row = row0 + wm + mt * 16 + g;
            int col = wn + nt * 8 + tig * 2;
            float* c = acc[mt][nt];
            if (col < 128) {
                if (row < N_NODES)
                    *reinterpret_cast<__half2*>(&ylh_out[(size_t)row * 128 + col]) =
                        __floats2half2_rn(c[0], c[1]);
                if (row + 8 < N_NODES)
                    *reinterpret_cast<__half2*>(&ylh_out[(size_t)(row + 8) * 128 + col]) =
                        __floats2half2_rn(c[2], c[3]);
            } else {
                int cr = col - 128;
                if (row < N_NODES)
                    *reinterpret_cast<float2*>(&yr_out[(size_t)row * 128 + cr]) = make_float2(c[0], c[1]);
                if (row + 8 < N_NODES)
                    *reinterpret_cast<float2*>(&yr_out[(size_t)(row + 8) * 128 + cr]) = make_float2(c[2], c[3]);
            }
        }
}

// ---------------- final combine + pool (layer 3) ----------------
__global__ __launch_bounds__(256)
void pool_combine_kernel(const __half* __restrict__ ylh_in, const float* __restrict__ yr_in,
                         const float* __restrict__ bias,
                         const int* __restrict__ batch, float* __restrict__ pooled) {
    int i = (blockIdx.x * blockDim.x + threadIdx.x) >> 5;
    if (i >= N_NODES) return;
    int lane = threadIdx.x & 31;
    int e0 = g_row_start[i], e1 = g_row_start[i + 1];
    float4 acc0 = make_float4(0, 0, 0, 0), acc1 = make_float4(0, 0, 0, 0);
    float4 acc2 = make_float4(0, 0, 0, 0), acc3 = make_float4(0, 0, 0, 0);
    int e = e0;
    const int lo4 = lane * 4;
    for (; e + 4 <= e1; e += 4) {
        int s0 = g_csr_src[e], s1 = g_csr_src[e + 1];
        int s2 = g_csr_src[e + 2], s3 = g_csr_src[e + 3];
        acc_half4(acc0, &ylh_in[(size_t)s0 * 128 + lo4]);
        acc_half4(acc1, &ylh_in[(size_t)s1 * 128 + lo4]);
        acc_half4(acc2, &ylh_in[(size_t)s2 * 128 + lo4]);
        acc_half4(acc3, &ylh_in[(size_t)s3 * 128 + lo4]);
    }
    for (; e < e1; e++) {
        int s0 = g_csr_src[e];
        acc_half4(acc0, &ylh_in[(size_t)s0 * 128 + lo4]);
    }
    acc0.x += acc1.x + acc2.x + acc3.x;
    acc0.y += acc1.y + acc2.y + acc3.y;
    acc0.z += acc1.z + acc2.z + acc3.z;
    acc0.w += acc1.w + acc2.w + acc3.w;

    float inv = g_inv_deg[i];
    float4 yr = *reinterpret_cast<const float4*>(&yr_in[(size_t)i * 128 + lo4]);
    float4 bb = *reinterpret_cast<const float4*>(&bias[lo4]);
    float4 r;
    r.x = fmaxf(fmaf(acc0.x, inv, yr.x + bb.x), 0.0f);
    r.y = fmaxf(fmaf(acc0.y, inv, yr.y + bb.y), 0.0f);
    r.z = fmaxf(fmaf(acc0.z, inv, yr.z + bb.z), 0.0f);
    r.w = fmaxf(fmaf(acc0.w, inv, yr.w + bb.w), 0.0f);
    int g = batch[i];
    float* p = &pooled[(size_t)g * HID + lo4];
    atomicAdd(p + 0, r.x);
    atomicAdd(p + 1, r.y);
    atomicAdd(p + 2, r.z);
    atomicAdd(p + 3, r.w);
}

// ---------------- final divide ----------------
__global__ void div_kernel(float* __restrict__ pooled) {
    int idx = blockIdx.x * blockDim.x + threadIdx.x;
    if (idx < N_GRAPHS * HID) {
        int g = idx >> 7;
        pooled[idx] *= 1.0f / fmaxf((float)g_counts[g], 1.0f);
    }
}

// ---------------- launch ----------------
extern "C" void kernel_launch(void* const* d_in, const int* in_sizes, int n_in,
                              void* d_out, int out_size) {
    const float* x     = (const float*)d_in[0];
    const int*   ei    = (const int*)d_in[1];
    const int*   batch = (const int*)d_in[2];
    const float* W1l = (const float*)d_in[3];
    const float* W1r = (const float*)d_in[4];
    const float* b1  = (const float*)d_in[5];
    const float* W2l = (const float*)d_in[6];
    const float* W2r = (const float*)d_in[7];
    const float* b2  = (const float*)d_in[8];
    const float* W3l = (const float*)d_in[9];
    const float* W3r = (const float*)d_in[10];
    const float* b3  = (const float*)d_in[11];
    float* pooled = (float*)d_out;

    __half *ylhA, *ylhB;
    float *yrA, *yrB;
    __nv_bfloat16 *whi, *wlo;
    cudaGetSymbolAddress((void**)&ylhA, g_ylhA);
    cudaGetSymbolAddress((void**)&yrA,  g_yrA);
    cudaGetSymbolAddress((void**)&ylhB, g_ylhB);
    cudaGetSymbolAddress((void**)&yrB,  g_yrB);
    cudaGetSymbolAddress((void**)&whi,  g_whi);
    cudaGetSymbolAddress((void**)&wlo,  g_wlo);

    cudaFuncSetAttribute(gemm_tc_kernel<0>, cudaFuncAttributeMaxDynamicSharedMemorySize, SM_TOT);
    cudaFuncSetAttribute(gemm_tc_kernel<1>, cudaFuncAttributeMaxDynamicSharedMemorySize, SM_TOT);

    const int nscan = (N_NODES + 1023) / 1024;   // 49

    init_kernel<<<256, 256>>>(pooled, W1l, W1r, W2l, W2r, W3l, W3r);
    hist_kernel<<<(N_EDGES / 4 + 255) / 256, 256>>>(ei, batch);
    scanA_kernel<<<nscan, 1024>>>();
    scanC_kernel<<<nscan, 1024>>>(nscan);
    csr_kernel<<<(N_EDGES / 4 + 255) / 256, 256>>>(ei);

    const int ntiles = (N_NODES + 127) / 128;

    // layer 1: A from x
    gemm_tc_kernel<0><<<ntiles, 256, SM_TOT>>>(x, nullptr, nullptr, nullptr,
                                               whi, wlo, ylhA, yrA);
    // layer 2: A = combine(layer1, b1) fused in staging
    gemm_tc_kernel<1><<<ntiles, 256, SM_TOT>>>(nullptr, ylhA, yrA, b1,
                                               whi + 256 * 128, wlo + 256 * 128, ylhB, yrB);
    // layer 3: A = combine(layer2, b2) fused in staging
    gemm_tc_kernel<1><<<ntiles, 256, SM_TOT>>>(nullptr, ylhB, yrB, b2,
                                               whi + 2 * 256 * 128, wlo + 2 * 256 * 128, ylhA, yrA);
    // final combine + pool
    pool_combine_kernel<<<N_NODES / 8, 256>>>(ylhA, yrA, b3, batch, pooled);

    div_kernel<<<(N_GRAPHS * HID + 255) / 256, 256>>>(pooled);
}

// round 14
// speedup vs baseline: 1.4354x; 1.4354x over previous
#include <cuda_runtime.h>
#include <cuda_bf16.h>
#include <cuda_fp16.h>
#include <cstdint>

#define N_NODES  50000
#define N_EDGES  800000
#define HID      128
#define N_GRAPHS 512

// ---------------- scratch ----------------
__device__ int   g_deg[N_NODES];
__device__ int   g_tmp_incl[N_NODES];
__device__ int   g_bsum[64];
__device__ int   g_cursor[N_NODES];
__device__ int   g_row_start[N_NODES + 1];
__device__ int   g_counts[N_GRAPHS];
__device__ int   g_csr_src[N_EDGES];
__device__ float g_inv_deg[N_NODES];

__device__ __half g_ylh[(size_t)N_NODES * 128];   // left-branch product, fp16 (gathered)
__device__ float  g_yr[(size_t)N_NODES * 128];    // right-branch product, fp32 (own row)

// bf16 hi/lo activation buffers (split precision)
__device__ __nv_bfloat16 g_xhi[(size_t)N_NODES * HID];
__device__ __nv_bfloat16 g_xlo[(size_t)N_NODES * HID];
__device__ __nv_bfloat16 g_hhi0[(size_t)N_NODES * HID];
__device__ __nv_bfloat16 g_hlo0[(size_t)N_NODES * HID];
__device__ __nv_bfloat16 g_hhi1[(size_t)N_NODES * HID];
__device__ __nv_bfloat16 g_hlo1[(size_t)N_NODES * HID];
// converted weights: [layer][256 rows (Wl then Wr)][128 k]
__device__ __nv_bfloat16 g_whi[3 * 256 * 128];
__device__ __nv_bfloat16 g_wlo[3 * 256 * 128];

// ---------------- init: zero deg/counts/pooled ----------------
__global__ void init_kernel(float* __restrict__ pooled) {
    int i = blockIdx.x * blockDim.x + threadIdx.x;
    int stride = gridDim.x * blockDim.x;
    for (int j = i; j < N_NODES; j += stride) g_deg[j] = 0;
    for (int j = i; j < N_GRAPHS; j += stride) g_counts[j] = 0;
    for (int j = i; j < N_GRAPHS * HID; j += stride) pooled[j] = 0.0f;
}

// ---------------- histograms: 4 edges/thread (int4) ----------------
__global__ void hist_kernel(const int* __restrict__ ei, const int* __restrict__ batch) {
    int q = blockIdx.x * blockDim.x + threadIdx.x;
    if (q < N_EDGES / 4) {
        int4 d = *reinterpret_cast<const int4*>(&ei[N_EDGES + q * 4]);
        atomicAdd(&g_deg[d.x], 1);
        atomicAdd(&g_deg[d.y], 1);
        atomicAdd(&g_deg[d.z], 1);
        atomicAdd(&g_deg[d.w], 1);
    }
    if (q < N_NODES / 4) {
        int4 b = *reinterpret_cast<const int4*>(&batch[q * 4]);
        atomicAdd(&g_counts[b.x], 1);
        atomicAdd(&g_counts[b.y], 1);
        atomicAdd(&g_counts[b.z], 1);
        atomicAdd(&g_counts[b.w], 1);
    }
}

// ---------------- scan A: per-block inclusive scans of deg ----------------
__global__ __launch_bounds__(1024)
void scanA_kernel() {
    __shared__ int wsum[32];
    const int t = threadIdx.x, lane = t & 31, wid = t >> 5;
    const int i = blockIdx.x * 1024 + t;
    int v = (i < N_NODES) ? g_deg[i] : 0;
    int x = v;
#pragma unroll
    for (int o = 1; o < 32; o <<= 1) {
        int y = __shfl_up_sync(0xffffffffu, x, o);
        if (lane >= o) x += y;
    }
    if (lane == 31) wsum[wid] = x;
    __syncthreads();
    if (wid == 0) {
        int w = wsum[lane];
#pragma unroll
        for (int o = 1; o < 32; o <<= 1) {
            int y = __shfl_up_sync(0xffffffffu, w, o);
            if (lane >= o) w += y;
        }
        wsum[lane] = w;
    }
    __syncthreads();
    int incl = x + (wid ? wsum[wid - 1] : 0);
    if (i < N_NODES) g_tmp_incl[i] = incl;
    if (t == 1023) g_bsum[blockIdx.x] = incl;
}

// ---------------- scan C: redundant 64-wide block-sum scan + finalize ----------------
__global__ __launch_bounds__(1024)
void scanC_kernel(int nblocks) {
    __shared__ int s[64];
    const int t = threadIdx.x;
    if (t < 64) s[t] = (t < nblocks) ? g_bsum[t] : 0;
    __syncthreads();
#pragma unroll
    for (int o = 1; o < 64; o <<= 1) {
        int v = 0;
        if (t < 64 && t >= o) v = s[t - o];
        __syncthreads();
        if (t < 64) s[t] += v;
        __syncthreads();
    }
    const int i = blockIdx.x * 1024 + t;
    if (i >= N_NODES) return;
    int boff = blockIdx.x ? s[blockIdx.x - 1] : 0;
    int d = g_deg[i];
    int rs = boff + g_tmp_incl[i] - d;
    g_row_start[i] = rs;
    g_cursor[i]    = rs;
    g_inv_deg[i]   = 1.0f / fmaxf((float)d, 1.0f);
    if (i == N_NODES - 1) g_row_start[N_NODES] = rs + d;
}

// ---------------- CSR fill: 4 edges/thread (int4) ----------------
__global__ void csr_kernel(const int* __restrict__ ei) {
    int q = blockIdx.x * blockDim.x + threadIdx.x;
    if (q >= N_EDGES / 4) return;
    int4 s = *reinterpret_cast<const int4*>(&ei[q * 4]);
    int4 d = *reinterpret_cast<const int4*>(&ei[N_EDGES + q * 4]);
    int p0 = atomicAdd(&g_cursor[d.x], 1);
    int p1 = atomicAdd(&g_cursor[d.y], 1);
    int p2 = atomicAdd(&g_cursor[d.z], 1);
    int p3 = atomicAdd(&g_cursor[d.w], 1);
    g_csr_src[p0] = s.x;
    g_csr_src[p1] = s.y;
    g_csr_src[p2] = s.z;
    g_csr_src[p3] = s.w;
}

// ---------------- split helpers ----------------
__device__ __forceinline__ void split1(float v, __nv_bfloat16& hi, __nv_bfloat16& lo) {
    hi = __float2bfloat16_rn(v);
    lo = __float2bfloat16_rn(v - __bfloat162float(hi));
}

// ---------------- convert x and weights -> bf16 hi/lo (merged) ----------------
__global__ void conv_kernel(const float* __restrict__ x,
                            const float* __restrict__ W1l, const float* __restrict__ W1r,
                            const float* __restrict__ W2l, const float* __restrict__ W2r,
                            const float* __restrict__ W3l, const float* __restrict__ W3r) {
    int i = blockIdx.x * blockDim.x + threadIdx.x;   // one float4 of x per thread
    if (i < N_NODES * HID / 4) {
        float4 v = *reinterpret_cast<const float4*>(&x[(size_t)i * 4]);
        __nv_bfloat16 h0, h1, h2, h3, l0, l1, l2, l3;
        split1(v.x, h0, l0); split1(v.y, h1, l1); split1(v.z, h2, l2); split1(v.w, h3, l3);
        __nv_bfloat16* ph = &g_xhi[(size_t)i * 4];
        __nv_bfloat16* pl = &g_xlo[(size_t)i * 4];
        ph[0] = h0; ph[1] = h1; ph[2] = h2; ph[3] = h3;
        pl[0] = l0; pl[1] = l1; pl[2] = l2; pl[3] = l3;
    }
    if (i < 3 * 256 * 128) {
        int layer = i / (256 * 128);
        int rem = i % (256 * 128);
        int n = rem / 128, k = rem % 128;
        const float* Wp;
        if (layer == 0) Wp = (n < 128) ? W1l : W1r;
        else if (layer == 1) Wp = (n < 128) ? W2l : W2r;
        else Wp = (n < 128) ? W3l : W3r;
        float v = Wp[(n & 127) * 128 + k];
        __nv_bfloat16 hi, lo;
        split1(v, hi, lo);
        g_whi[i] = hi;
        g_wlo[i] = lo;
    }
}

// ---------------- mma.sync bf16 GEMM: [yl(fp16) | yr(fp32)] = A @ [Wl^T | Wr^T] ----------------
// bf16x2 split: D = Ahi@Bhi + Ahi@Blo + Alo@Bhi (fp32 accum)
#define ASTR 136                       // smem row stride in bf16 elems (conflict-free)
static const int SM_AHI = 0;
static const int SM_ALO = SM_AHI + 128 * ASTR * 2;   // 34816
static const int SM_BHI = SM_ALO + 128 * ASTR * 2;   // 69632
static const int SM_BLO = SM_BHI + 256 * ASTR * 2;   // 139264
static const int SM_TOT = SM_BLO + 256 * ASTR * 2;   // 208896

__device__ __forceinline__ void mma16816(float* c, const uint32_t* a, const uint32_t* b) {
    asm volatile(
        "mma.sync.aligned.m16n8k16.row.col.f32.bf16.bf16.f32 "
        "{%0,%1,%2,%3}, {%4,%5,%6,%7}, {%8,%9}, {%0,%1,%2,%3};"
        : "+f"(c[0]), "+f"(c[1]), "+f"(c[2]), "+f"(c[3])
        : "r"(a[0]), "r"(a[1]), "r"(a[2]), "r"(a[3]), "r"(b[0]), "r"(b[1]));
}

__global__ __launch_bounds__(256, 1)
void gemm_tc_kernel(const __nv_bfloat16* __restrict__ Ahi, const __nv_bfloat16* __restrict__ Alo,
                    const __nv_bfloat16* __restrict__ Whi, const __nv_bfloat16* __restrict__ Wlo) {
    extern __shared__ char smem[];
    const int t = threadIdx.x;
    const int row0 = blockIdx.x * 128;

    // ---- stage A (128x128 bf16 hi/lo) ----
#pragma unroll
    for (int i = t; i < 128 * 16; i += 256) {
        int r = i >> 4, k = (i & 15) * 8;
        int row = row0 + r;
        uint4 vh = make_uint4(0, 0, 0, 0), vl = make_uint4(0, 0, 0, 0);
        if (row < N_NODES) {
            vh = *reinterpret_cast<const uint4*>(&Ahi[(size_t)row * HID + k]);
            vl = *reinterpret_cast<const uint4*>(&Alo[(size_t)row * HID + k]);
        }
        *reinterpret_cast<uint4*>(smem + SM_AHI + (r * ASTR + k) * 2) = vh;
        *reinterpret_cast<uint4*>(smem + SM_ALO + (r * ASTR + k) * 2) = vl;
    }
    // ---- stage B (256x128 bf16 hi/lo) ----
#pragma unroll
    for (int i = t; i < 256 * 16; i += 256) {
        int n = i >> 4, k = (i & 15) * 8;
        *reinterpret_cast<uint4*>(smem + SM_BHI + (n * ASTR + k) * 2) =
            *reinterpret_cast<const uint4*>(&Whi[n * HID + k]);
        *reinterpret_cast<uint4*>(smem + SM_BLO + (n * ASTR + k) * 2) =
            *reinterpret_cast<const uint4*>(&Wlo[n * HID + k]);
    }
    __syncthreads();

    const int wid = t >> 5, lane = t & 31;
    const int g = lane >> 2, tig = lane & 3;
    const int wm = (wid & 1) * 64;        // warp M offset (2 warps in M)
    const int wn = (wid >> 1) * 64;       // warp N offset (4 warps in N)

    float acc[4][8][4];
#pragma unroll
    for (int a = 0; a < 4; a++)
#pragma unroll
        for (int b = 0; b < 8; b++)
#pragma unroll
            for (int c = 0; c < 4; c++) acc[a][b][c] = 0.0f;

    for (int ks = 0; ks < 8; ks++) {
        const int k0 = ks * 16 + tig * 2;
        uint32_t ah[4][4], al[4][4];
#pragma unroll
        for (int mt = 0; mt < 4; mt++) {
            int base = ((wm + mt * 16 + g) * ASTR + k0) * 2;
            ah[mt][0] = *reinterpret_cast<const uint32_t*>(smem + SM_AHI + base);
            ah[mt][1] = *reinterpret_cast<const uint32_t*>(smem + SM_AHI + base + 8 * ASTR * 2);
            ah[mt][2] = *reinterpret_cast<const uint32_t*>(smem + SM_AHI + base + 16);
            ah[mt][3] = *reinterpret_cast<const uint32_t*>(smem + SM_AHI + base + 8 * ASTR * 2 + 16);
            al[mt][0] = *reinterpret_cast<const uint32_t*>(smem + SM_ALO + base);
            al[mt][1] = *reinterpret_cast<const uint32_t*>(smem + SM_ALO + base + 8 * ASTR * 2);
            al[mt][2] = *reinterpret_cast<const uint32_t*>(smem + SM_ALO + base + 16);
            al[mt][3] = *reinterpret_cast<const uint32_t*>(smem + SM_ALO + base + 8 * ASTR * 2 + 16);
        }
#pragma unroll
        for (int nh = 0; nh < 2; nh++) {
            uint32_t bh[4][2], bl[4][2];
#pragma unroll
            for (int nt = 0; nt < 4; nt++) {
                int base = ((wn + nh * 32 + nt * 8 + g) * ASTR + k0) * 2;
                bh[nt][0] = *reinterpret_cast<const uint32_t*>(smem + SM_BHI + base);
                bh[nt][1] = *reinterpret_cast<const uint32_t*>(smem + SM_BHI + base + 16);
                bl[nt][0] = *reinterpret_cast<const uint32_t*>(smem + SM_BLO + base);
                bl[nt][1] = *reinterpret_cast<const uint32_t*>(smem + SM_BLO + base + 16);
            }
#pragma unroll
            for (int mt = 0; mt < 4; mt++)
#pragma unroll
                for (int nt = 0; nt < 4; nt++) {
                    float* c = acc[mt][nh * 4 + nt];
                    mma16816(c, ah[mt], bh[nt]);
                    mma16816(c, ah[mt], bl[nt]);
                    mma16816(c, al[mt], bh[nt]);
                }
        }
    }

    // ---- epilogue: cols [0,128) -> fp16 g_ylh ; cols [128,256) -> fp32 g_yr ----
#pragma unroll
    for (int mt = 0; mt < 4; mt++)
#pragma unroll
        for (int nt = 0; nt < 8; nt++) {
            int row = row0 + wm + mt * 16 + g;
            int col = wn + nt * 8 + tig * 2;
            float* c = acc[mt][nt];
            if (col < 128) {
                if (row < N_NODES)
                    *reinterpret_cast<__half2*>(&g_ylh[(size_t)row * 128 + col]) =
                        __floats2half2_rn(c[0], c[1]);
                if (row + 8 < N_NODES)
                    *reinterpret_cast<__half2*>(&g_ylh[(size_t)(row + 8) * 128 + col]) =
                        __floats2half2_rn(c[2], c[3]);
            } else {
                int cr = col - 128;
                if (row < N_NODES)
                    *reinterpret_cast<float2*>(&g_yr[(size_t)row * 128 + cr]) = make_float2(c[0], c[1]);
                if (row + 8 < N_NODES)
                    *reinterpret_cast<float2*>(&g_yr[(size_t)(row + 8) * 128 + cr]) = make_float2(c[2], c[3]);
            }
        }
}

// ---------------- combine: 32 lanes/node, 4-chain unroll, uint2 fp16 gathers ----------------
__device__ __forceinline__ void acc_half4(float4& acc, const __half* p) {
    uint2 u = *reinterpret_cast<const uint2*>(p);
    float2 f0 = __half22float2(*reinterpret_cast<__half2*>(&u.x));
    float2 f1 = __half22float2(*reinterpret_cast<__half2*>(&u.y));
    acc.x += f0.x; acc.y += f0.y; acc.z += f1.x; acc.w += f1.y;
}

__global__ __launch_bounds__(256)
void combine_kernel(const float* __restrict__ bias,
                    __nv_bfloat16* __restrict__ Hhi, __nv_bfloat16* __restrict__ Hlo,
                    const int* __restrict__ batch, float* __restrict__ pooled,
                    int do_pool) {
    int i = (blockIdx.x * blockDim.x + threadIdx.x) >> 5;
    if (i >= N_NODES) return;
    int lane = threadIdx.x & 31;
    int e0 = g_row_start[i], e1 = g_row_start[i + 1];
    float4 acc0 = make_float4(0, 0, 0, 0), acc1 = make_float4(0, 0, 0, 0);
    float4 acc2 = make_float4(0, 0, 0, 0), acc3 = make_float4(0, 0, 0, 0);
    int e = e0;
    const int lo4 = lane * 4;
    for (; e + 4 <= e1; e += 4) {
        int s0 = g_csr_src[e], s1 = g_csr_src[e + 1];
        int s2 = g_csr_src[e + 2], s3 = g_csr_src[e + 3];
        acc_half4(acc0, &g_ylh[(size_t)s0 * 128 + lo4]);
        acc_half4(acc1, &g_ylh[(size_t)s1 * 128 + lo4]);
        acc_half4(acc2, &g_ylh[(size_t)s2 * 128 + lo4]);
        acc_half4(acc3, &g_ylh[(size_t)s3 * 128 + lo4]);
    }
    for (; e < e1; e++) {
        int s0 = g_csr_src[e];
        acc_half4(acc0, &g_ylh[(size_t)s0 * 128 + lo4]);
    }
    acc0.x += acc1.x + acc2.x + acc3.x;
    acc0.y += acc1.y + acc2.y + acc3.y;
    acc0.z += acc1.z + acc2.z + acc3.z;
    acc0.w += acc1.w + acc2.w + acc3.w;

    float inv = g_inv_deg[i];
    float4 yr = *reinterpret_cast<const float4*>(&g_yr[(size_t)i * 128 + lo4]);
    float4 bb = *reinterpret_cast<const float4*>(&bias[lo4]);
    float4 r;
    r.x = fmaxf(fmaf(acc0.x, inv, yr.x + bb.x), 0.0f);
    r.y = fmaxf(fmaf(acc0.y, inv, yr.y + bb.y), 0.0f);
    r.z = fmaxf(fmaf(acc0.z, inv, yr.z + bb.z), 0.0f);
    r.w = fmaxf(fmaf(acc0.w, inv, yr.w + bb.w), 0.0f);
    if (!do_pool) {
        __nv_bfloat16 h0, h1, h2, h3, l0, l1, l2, l3;
        split1(r.x, h0, l0); split1(r.y, h1, l1); split1(r.z, h2, l2); split1(r.w, h3, l3);
        __nv_bfloat16* ph = &Hhi[(size_t)i * HID + lo4];
        __nv_bfloat16* pl = &Hlo[(size_t)i * HID + lo4];
        ph[0] = h0; ph[1] = h1; ph[2] = h2; ph[3] = h3;
        pl[0] = l0; pl[1] = l1; pl[2] = l2; pl[3] = l3;
    } else {
        int g = batch[i];
        float* p = &pooled[(size_t)g * HID + lo4];
        atomicAdd(p + 0, r.x);
        atomicAdd(p + 1, r.y);
        atomicAdd(p + 2, r.z);
        atomicAdd(p + 3, r.w);
    }
}

// ---------------- final divide ----------------
__global__ void div_kernel(float* __restrict__ pooled) {
    int idx = blockIdx.x * blockDim.x + threadIdx.x;
    if (idx < N_GRAPHS * HID) {
        int g = idx >> 7;
        pooled[idx] *= 1.0f / fmaxf((float)g_counts[g], 1.0f);
    }
}

// ---------------- launch ----------------
extern "C" void kernel_launch(void* const* d_in, const int* in_sizes, int n_in,
                              void* d_out, int out_size) {
    const float* x     = (const float*)d_in[0];
    const int*   ei    = (const int*)d_in[1];
    const int*   batch = (const int*)d_in[2];
    const float* W1l = (const float*)d_in[3];
    const float* W1r = (const float*)d_in[4];
    const float* b1  = (const float*)d_in[5];
    const float* W2l = (const float*)d_in[6];
    const float* W2r = (const float*)d_in[7];
    const float* b2  = (const float*)d_in[8];
    const float* W3l = (const float*)d_in[9];
    const float* W3r = (const float*)d_in[10];
    const float* b3  = (const float*)d_in[11];
    float* pooled = (float*)d_out;

    __nv_bfloat16 *xhi, *xlo, *hhi0, *hlo0, *hhi1, *hlo1, *whi, *wlo;
    cudaGetSymbolAddress((void**)&xhi,  g_xhi);
    cudaGetSymbolAddress((void**)&xlo,  g_xlo);
    cudaGetSymbolAddress((void**)&hhi0, g_hhi0);
    cudaGetSymbolAddress((void**)&hlo0, g_hlo0);
    cudaGetSymbolAddress((void**)&hhi1, g_hhi1);
    cudaGetSymbolAddress((void**)&hlo1, g_hlo1);
    cudaGetSymbolAddress((void**)&whi,  g_whi);
    cudaGetSymbolAddress((void**)&wlo,  g_wlo);

    cudaFuncSetAttribute(gemm_tc_kernel, cudaFuncAttributeMaxDynamicSharedMemorySize, SM_TOT);

    // lazy one-time stream/event creation (first call is the uncaptured correctness run)
    static cudaStream_t s2 = nullptr;
    static cudaEvent_t evFork = nullptr, evJoin = nullptr;
    if (!s2) {
        cudaStreamCreateWithFlags(&s2, cudaStreamNonBlocking);
        cudaEventCreateWithFlags(&evFork, cudaEventDisableTiming);
        cudaEventCreateWithFlags(&evJoin, cudaEventDisableTiming);
    }

    const int nscan = (N_NODES + 1023) / 1024;   // 49
    const int ntiles = (N_NODES + 127) / 128;

    // ---- fork: graph-setup chain on s2, concurrent with conv+gemm1 on default ----
    cudaEventRecord(evFork, 0);
    cudaStreamWaitEvent(s2, evFork, 0);

    init_kernel<<<256, 256, 0, s2>>>(pooled);
    hist_kernel<<<(N_EDGES / 4 + 255) / 256, 256, 0, s2>>>(ei, batch);
    scanA_kernel<<<nscan, 1024, 0, s2>>>();
    scanC_kernel<<<nscan, 1024, 0, s2>>>(nscan);
    csr_kernel<<<(N_EDGES / 4 + 255) / 256, 256, 0, s2>>>(ei);
    cudaEventRecord(evJoin, s2);

    // default stream: weight/x conversion then layer-1 GEMM (independent of CSR)
    conv_kernel<<<(N_NODES * HID / 4 + 255) / 256, 256>>>(x, W1l, W1r, W2l, W2r, W3l, W3r);
    gemm_tc_kernel<<<ntiles, 256, SM_TOT>>>(xhi, xlo, whi, wlo);

    // ---- join before first combine (needs CSR + inv_deg) ----
    cudaStreamWaitEvent(0, evJoin, 0);

    combine_kernel<<<N_NODES / 8, 256>>>(b1, hhi0, hlo0, nullptr, nullptr, 0);
    // layer 2
    gemm_tc_kernel<<<ntiles, 256, SM_TOT>>>(hhi0, hlo0, whi + 256 * 128, wlo + 256 * 128);
    combine_kernel<<<N_NODES / 8, 256>>>(b2, hhi1, hlo1, nullptr, nullptr, 0);
    // layer 3 (pool fused)
    gemm_tc_kernel<<<ntiles, 256, SM_TOT>>>(hhi1, hlo1, whi + 2 * 256 * 128, wlo + 2 * 256 * 128);
    combine_kernel<<<N_NODES / 8, 256>>>(b3, nullptr, nullptr, batch, pooled, 1);

    div_kernel<<<(N_GRAPHS * HID + 255) / 256, 256>>>(pooled);
}

// round 15
// speedup vs baseline: 1.6614x; 1.1575x over previous
#include <cuda_runtime.h>
#include <cuda_bf16.h>
#include <cuda_fp16.h>
#include <cstdint>

#define N_NODES  50000
#define N_EDGES  800000
#define HID      128
#define N_GRAPHS 512

// ---------------- scratch ----------------
__device__ int   g_deg[N_NODES];
__device__ int   g_tmp_incl[N_NODES];
__device__ int   g_bsum[64];
__device__ int   g_cursor[N_NODES];
__device__ int   g_row_start[N_NODES + 1];
__device__ int   g_counts[N_GRAPHS];
__device__ int   g_csr_src[N_EDGES];
__device__ float g_inv_deg[N_NODES];

__device__ __half g_ylh[(size_t)N_NODES * 128];   // left-branch product, fp16 (gathered)
__device__ float  g_yr[(size_t)N_NODES * 128];    // right-branch product, fp32 (own row)

// single-bf16 activation buffers (weights keep hi/lo split; activations are bf16)
__device__ __nv_bfloat16 g_xb[(size_t)N_NODES * HID];
__device__ __nv_bfloat16 g_hb0[(size_t)N_NODES * HID];
__device__ __nv_bfloat16 g_hb1[(size_t)N_NODES * HID];
// converted weights: [layer][256 rows (Wl then Wr)][128 k]
__device__ __nv_bfloat16 g_whi[3 * 256 * 128];
__device__ __nv_bfloat16 g_wlo[3 * 256 * 128];

// ---------------- init: zero deg/counts/pooled ----------------
__global__ void init_kernel(float* __restrict__ pooled) {
    int i = blockIdx.x * blockDim.x + threadIdx.x;
    int stride = gridDim.x * blockDim.x;
    for (int j = i; j < N_NODES; j += stride) g_deg[j] = 0;
    for (int j = i; j < N_GRAPHS; j += stride) g_counts[j] = 0;
    for (int j = i; j < N_GRAPHS * HID; j += stride) pooled[j] = 0.0f;
}

// ---------------- histograms: 4 edges/thread (int4) ----------------
__global__ void hist_kernel(const int* __restrict__ ei, const int* __restrict__ batch) {
    int q = blockIdx.x * blockDim.x + threadIdx.x;
    if (q < N_EDGES / 4) {
        int4 d = *reinterpret_cast<const int4*>(&ei[N_EDGES + q * 4]);
        atomicAdd(&g_deg[d.x], 1);
        atomicAdd(&g_deg[d.y], 1);
        atomicAdd(&g_deg[d.z], 1);
        atomicAdd(&g_deg[d.w], 1);
    }
    if (q < N_NODES / 4) {
        int4 b = *reinterpret_cast<const int4*>(&batch[q * 4]);
        atomicAdd(&g_counts[b.x], 1);
        atomicAdd(&g_counts[b.y], 1);
        atomicAdd(&g_counts[b.z], 1);
        atomicAdd(&g_counts[b.w], 1);
    }
}

// ---------------- scan A: per-block inclusive scans of deg ----------------
__global__ __launch_bounds__(1024)
void scanA_kernel() {
    __shared__ int wsum[32];
    const int t = threadIdx.x, lane = t & 31, wid = t >> 5;
    const int i = blockIdx.x * 1024 + t;
    int v = (i < N_NODES) ? g_deg[i] : 0;
    int x = v;
#pragma unroll
    for (int o = 1; o < 32; o <<= 1) {
        int y = __shfl_up_sync(0xffffffffu, x, o);
        if (lane >= o) x += y;
    }
    if (lane == 31) wsum[wid] = x;
    __syncthreads();
    if (wid == 0) {
        int w = wsum[lane];
#pragma unroll
        for (int o = 1; o < 32; o <<= 1) {
            int y = __shfl_up_sync(0xffffffffu, w, o);
            if (lane >= o) w += y;
        }
        wsum[lane] = w;
    }
    __syncthreads();
    int incl = x + (wid ? wsum[wid - 1] : 0);
    if (i < N_NODES) g_tmp_incl[i] = incl;
    if (t == 1023) g_bsum[blockIdx.x] = incl;
}

// ---------------- scan C: redundant 64-wide block-sum scan + finalize ----------------
__global__ __launch_bounds__(1024)
void scanC_kernel(int nblocks) {
    __shared__ int s[64];
    const int t = threadIdx.x;
    if (t < 64) s[t] = (t < nblocks) ? g_bsum[t] : 0;
    __syncthreads();
#pragma unroll
    for (int o = 1; o < 64; o <<= 1) {
        int v = 0;
        if (t < 64 && t >= o) v = s[t - o];
        __syncthreads();
        if (t < 64) s[t] += v;
        __syncthreads();
    }
    const int i = blockIdx.x * 1024 + t;
    if (i >= N_NODES) return;
    int boff = blockIdx.x ? s[blockIdx.x - 1] : 0;
    int d = g_deg[i];
    int rs = boff + g_tmp_incl[i] - d;
    g_row_start[i] = rs;
    g_cursor[i]    = rs;
    g_inv_deg[i]   = 1.0f / fmaxf((float)d, 1.0f);
    if (i == N_NODES - 1) g_row_start[N_NODES] = rs + d;
}

// ---------------- CSR fill: 4 edges/thread (int4) ----------------
__global__ void csr_kernel(const int* __restrict__ ei) {
    int q = blockIdx.x * blockDim.x + threadIdx.x;
    if (q >= N_EDGES / 4) return;
    int4 s = *reinterpret_cast<const int4*>(&ei[q * 4]);
    int4 d = *reinterpret_cast<const int4*>(&ei[N_EDGES + q * 4]);
    int p0 = atomicAdd(&g_cursor[d.x], 1);
    int p1 = atomicAdd(&g_cursor[d.y], 1);
    int p2 = atomicAdd(&g_cursor[d.z], 1);
    int p3 = atomicAdd(&g_cursor[d.w], 1);
    g_csr_src[p0] = s.x;
    g_csr_src[p1] = s.y;
    g_csr_src[p2] = s.z;
    g_csr_src[p3] = s.w;
}

// ---------------- split helpers ----------------
__device__ __forceinline__ void split1(float v, __nv_bfloat16& hi, __nv_bfloat16& lo) {
    hi = __float2bfloat16_rn(v);
    lo = __float2bfloat16_rn(v - __bfloat162float(hi));
}
__device__ __forceinline__ uint32_t pack_bf2(float a, float b) {
    return ((uint32_t)__bfloat16_as_ushort(__float2bfloat16_rn(b)) << 16) |
           __bfloat16_as_ushort(__float2bfloat16_rn(a));
}

// ---------------- convert x (bf16 single) and weights (bf16 hi/lo) ----------------
__global__ void conv_kernel(const float* __restrict__ x,
                            const float* __restrict__ W1l, const float* __restrict__ W1r,
                            const float* __restrict__ W2l, const float* __restrict__ W2r,
                            const float* __restrict__ W3l, const float* __restrict__ W3r) {
    int i = blockIdx.x * blockDim.x + threadIdx.x;   // one float4 of x per thread
    if (i < N_NODES * HID / 4) {
        float4 v = *reinterpret_cast<const float4*>(&x[(size_t)i * 4]);
        uint2 u;
        u.x = pack_bf2(v.x, v.y);
        u.y = pack_bf2(v.z, v.w);
        *reinterpret_cast<uint2*>(&g_xb[(size_t)i * 4]) = u;
    }
    if (i < 3 * 256 * 128) {
        int layer = i / (256 * 128);
        int rem = i % (256 * 128);
        int n = rem / 128, k = rem % 128;
        const float* Wp;
        if (layer == 0) Wp = (n < 128) ? W1l : W1r;
        else if (layer == 1) Wp = (n < 128) ? W2l : W2r;
        else Wp = (n < 128) ? W3l : W3r;
        float v = Wp[(n & 127) * 128 + k];
        __nv_bfloat16 hi, lo;
        split1(v, hi, lo);
        g_whi[i] = hi;
        g_wlo[i] = lo;
    }
}

// ---------------- mma.sync bf16 GEMM: [yl(fp16) | yr(fp32)] = A @ [Wl^T | Wr^T] ----------------
// weight-only split: D = A@Bhi + A@Blo (fp32 accum); activations single bf16
#define ASTR 136                       // smem row stride in bf16 elems (conflict-free)
static const int SM_A   = 0;
static const int SM_BHI = SM_A + 128 * ASTR * 2;     // 34816
static const int SM_BLO = SM_BHI + 256 * ASTR * 2;   // 104448
static const int SM_TOT = SM_BLO + 256 * ASTR * 2;   // 174080

__device__ __forceinline__ void mma16816(float* c, const uint32_t* a, const uint32_t* b) {
    asm volatile(
        "mma.sync.aligned.m16n8k16.row.col.f32.bf16.bf16.f32 "
        "{%0,%1,%2,%3}, {%4,%5,%6,%7}, {%8,%9}, {%0,%1,%2,%3};"
        : "+f"(c[0]), "+f"(c[1]), "+f"(c[2]), "+f"(c[3])
        : "r"(a[0]), "r"(a[1]), "r"(a[2]), "r"(a[3]), "r"(b[0]), "r"(b[1]));
}

__global__ __launch_bounds__(256, 1)
void gemm_tc_kernel(const __nv_bfloat16* __restrict__ Ab,
                    const __nv_bfloat16* __restrict__ Whi, const __nv_bfloat16* __restrict__ Wlo) {
    extern __shared__ char smem[];
    const int t = threadIdx.x;
    const int row0 = blockIdx.x * 128;

    // ---- stage A (128x128 bf16) ----
#pragma unroll
    for (int i = t; i < 128 * 16; i += 256) {
        int r = i >> 4, k = (i & 15) * 8;
        int row = row0 + r;
        uint4 va = make_uint4(0, 0, 0, 0);
        if (row < N_NODES)
            va = *reinterpret_cast<const uint4*>(&Ab[(size_t)row * HID + k]);
        *reinterpret_cast<uint4*>(smem + SM_A + (r * ASTR + k) * 2) = va;
    }
    // ---- stage B (256x128 bf16 hi/lo) ----
#pragma unroll
    for (int i = t; i < 256 * 16; i += 256) {
        int n = i >> 4, k = (i & 15) * 8;
        *reinterpret_cast<uint4*>(smem + SM_BHI + (n * ASTR + k) * 2) =
            *reinterpret_cast<const uint4*>(&Whi[n * HID + k]);
        *reinterpret_cast<uint4*>(smem + SM_BLO + (n * ASTR + k) * 2) =
            *reinterpret_cast<const uint4*>(&Wlo[n * HID + k]);
    }
    __syncthreads();

    const int wid = t >> 5, lane = t & 31;
    const int g = lane >> 2, tig = lane & 3;
    const int wm = (wid & 1) * 64;        // warp M offset (2 warps in M)
    const int wn = (wid >> 1) * 64;       // warp N offset (4 warps in N)

    float acc[4][8][4];
#pragma unroll
    for (int a = 0; a < 4; a++)
#pragma unroll
        for (int b = 0; b < 8; b++)
#pragma unroll
            for (int c = 0; c < 4; c++) acc[a][b][c] = 0.0f;

    for (int ks = 0; ks < 8; ks++) {
        const int k0 = ks * 16 + tig * 2;
        uint32_t ah[4][4];
#pragma unroll
        for (int mt = 0; mt < 4; mt++) {
            int base = ((wm + mt * 16 + g) * ASTR + k0) * 2;
            ah[mt][0] = *reinterpret_cast<const uint32_t*>(smem + SM_A + base);
            ah[mt][1] = *reinterpret_cast<const uint32_t*>(smem + SM_A + base + 8 * ASTR * 2);
            ah[mt][2] = *reinterpret_cast<const uint32_t*>(smem + SM_A + base + 16);
            ah[mt][3] = *reinterpret_cast<const uint32_t*>(smem + SM_A + base + 8 * ASTR * 2 + 16);
        }
#pragma unroll
        for (int nh = 0; nh < 2; nh++) {
            uint32_t bh[4][2], bl[4][2];
#pragma unroll
            for (int nt = 0; nt < 4; nt++) {
                int base = ((wn + nh * 32 + nt * 8 + g) * ASTR + k0) * 2;
                bh[nt][0] = *reinterpret_cast<const uint32_t*>(smem + SM_BHI + base);
                bh[nt][1] = *reinterpret_cast<const uint32_t*>(smem + SM_BHI + base + 16);
                bl[nt][0] = *reinterpret_cast<const uint32_t*>(smem + SM_BLO + base);
                bl[nt][1] = *reinterpret_cast<const uint32_t*>(smem + SM_BLO + base + 16);
            }
#pragma unroll
            for (int mt = 0; mt < 4; mt++)
#pragma unroll
                for (int nt = 0; nt < 4; nt++) {
                    float* c = acc[mt][nh * 4 + nt];
                    mma16816(c, ah[mt], bh[nt]);
                    mma16816(c, ah[mt], bl[nt]);
                }
        }
    }

    // ---- epilogue: cols [0,128) -> fp16 g_ylh ; cols [128,256) -> fp32 g_yr ----
#pragma unroll
    for (int mt = 0; mt < 4; mt++)
#pragma unroll
        for (int nt = 0; nt < 8; nt++) {
            int row = row0 + wm + mt * 16 + g;
            int col = wn + nt * 8 + tig * 2;
            float* c = acc[mt][nt];
            if (col < 128) {
                if (row < N_NODES)
                    *reinterpret_cast<__half2*>(&g_ylh[(size_t)row * 128 + col]) =
                        __floats2half2_rn(c[0], c[1]);
                if (row + 8 < N_NODES)
                    *reinterpret_cast<__half2*>(&g_ylh[(size_t)(row + 8) * 128 + col]) =
                        __floats2half2_rn(c[2], c[3]);
            } else {
                int cr = col - 128;
                if (row < N_NODES)
                    *reinterpret_cast<float2*>(&g_yr[(size_t)row * 128 + cr]) = make_float2(c[0], c[1]);
                if (row + 8 < N_NODES)
                    *reinterpret_cast<float2*>(&g_yr[(size_t)(row + 8) * 128 + cr]) = make_float2(c[2], c[3]);
            }
        }
}

// ---------------- combine: 32 lanes/node, 4-chain unroll, uint2 fp16 gathers ----------------
__device__ __forceinline__ void acc_half4(float4& acc, const __half* p) {
    uint2 u = *reinterpret_cast<const uint2*>(p);
    float2 f0 = __half22float2(*reinterpret_cast<__half2*>(&u.x));
    float2 f1 = __half22float2(*reinterpret_cast<__half2*>(&u.y));
    acc.x += f0.x; acc.y += f0.y; acc.z += f1.x; acc.w += f1.y;
}

__global__ __launch_bounds__(256)
void combine_kernel(const float* __restrict__ bias,
                    __nv_bfloat16* __restrict__ Hout,
                    const int* __restrict__ batch, float* __restrict__ pooled,
                    int do_pool) {
    int i = (blockIdx.x * blockDim.x + threadIdx.x) >> 5;
    if (i >= N_NODES) return;
    int lane = threadIdx.x & 31;
    int e0 = g_row_start[i], e1 = g_row_start[i + 1];
    float4 acc0 = make_float4(0, 0, 0, 0), acc1 = make_float4(0, 0, 0, 0);
    float4 acc2 = make_float4(0, 0, 0, 0), acc3 = make_float4(0, 0, 0, 0);
    int e = e0;
    const int lo4 = lane * 4;
    for (; e + 4 <= e1; e += 4) {
        int s0 = g_csr_src[e], s1 = g_csr_src[e + 1];
        int s2 = g_csr_src[e + 2], s3 = g_csr_src[e + 3];
        acc_half4(acc0, &g_ylh[(size_t)s0 * 128 + lo4]);
        acc_half4(acc1, &g_ylh[(size_t)s1 * 128 + lo4]);
        acc_half4(acc2, &g_ylh[(size_t)s2 * 128 + lo4]);
        acc_half4(acc3, &g_ylh[(size_t)s3 * 128 + lo4]);
    }
    for (; e < e1; e++) {
        int s0 = g_csr_src[e];
        acc_half4(acc0, &g_ylh[(size_t)s0 * 128 + lo4]);
    }
    acc0.x += acc1.x + acc2.x + acc3.x;
    acc0.y += acc1.y + acc2.y + acc3.y;
    acc0.z += acc1.z + acc2.z + acc3.z;
    acc0.w += acc1.w + acc2.w + acc3.w;

    float inv = g_inv_deg[i];
    float4 yr = *reinterpret_cast<const float4*>(&g_yr[(size_t)i * 128 + lo4]);
    float4 bb = *reinterpret_cast<const float4*>(&bias[lo4]);
    float4 r;
    r.x = fmaxf(fmaf(acc0.x, inv, yr.x + bb.x), 0.0f);
    r.y = fmaxf(fmaf(acc0.y, inv, yr.y + bb.y), 0.0f);
    r.z = fmaxf(fmaf(acc0.z, inv, yr.z + bb.z), 0.0f);
    r.w = fmaxf(fmaf(acc0.w, inv, yr.w + bb.w), 0.0f);
    if (!do_pool) {
        uint2 u;
        u.x = pack_bf2(r.x, r.y);
        u.y = pack_bf2(r.z, r.w);
        *reinterpret_cast<uint2*>(&Hout[(size_t)i * HID + lo4]) = u;
    } else {
        int g = batch[i];
        float* p = &pooled[(size_t)g * HID + lo4];
        atomicAdd(p + 0, r.x);
        atomicAdd(p + 1, r.y);
        atomicAdd(p + 2, r.z);
        atomicAdd(p + 3, r.w);
    }
}

// ---------------- final divide ----------------
__global__ void div_kernel(float* __restrict__ pooled) {
    int idx = blockIdx.x * blockDim.x + threadIdx.x;
    if (idx < N_GRAPHS * HID) {
        int g = idx >> 7;
        pooled[idx] *= 1.0f / fmaxf((float)g_counts[g], 1.0f);
    }
}

// ---------------- launch ----------------
extern "C" void kernel_launch(void* const* d_in, const int* in_sizes, int n_in,
                              void* d_out, int out_size) {
    const float* x     = (const float*)d_in[0];
    const int*   ei    = (const int*)d_in[1];
    const int*   batch = (const int*)d_in[2];
    const float* W1l = (const float*)d_in[3];
    const float* W1r = (const float*)d_in[4];
    const float* b1  = (const float*)d_in[5];
    const float* W2l = (const float*)d_in[6];
    const float* W2r = (const float*)d_in[7];
    const float* b2  = (const float*)d_in[8];
    const float* W3l = (const float*)d_in[9];
    const float* W3r = (const float*)d_in[10];
    const float* b3  = (const float*)d_in[11];
    float* pooled = (float*)d_out;

    __nv_bfloat16 *xb, *hb0, *hb1, *whi, *wlo;
    cudaGetSymbolAddress((void**)&xb,  g_xb);
    cudaGetSymbolAddress((void**)&hb0, g_hb0);
    cudaGetSymbolAddress((void**)&hb1, g_hb1);
    cudaGetSymbolAddress((void**)&whi, g_whi);
    cudaGetSymbolAddress((void**)&wlo, g_wlo);

    cudaFuncSetAttribute(gemm_tc_kernel, cudaFuncAttributeMaxDynamicSharedMemorySize, SM_TOT);

    // lazy one-time stream/event creation (first call is the uncaptured correctness run)
    static cudaStream_t s2 = nullptr;
    static cudaEvent_t evFork = nullptr, evJoin = nullptr;
    if (!s2) {
        cudaStreamCreateWithFlags(&s2, cudaStreamNonBlocking);
        cudaEventCreateWithFlags(&evFork, cudaEventDisableTiming);
        cudaEventCreateWithFlags(&evJoin, cudaEventDisableTiming);
    }

    const int nscan = (N_NODES + 1023) / 1024;   // 49
    const int ntiles = (N_NODES + 127) / 128;

    // ---- fork: graph-setup chain on s2, concurrent with conv+gemm1 on default ----
    cudaEventRecord(evFork, 0);
    cudaStreamWaitEvent(s2, evFork, 0);

    init_kernel<<<256, 256, 0, s2>>>(pooled);
    hist_kernel<<<(N_EDGES / 4 + 255) / 256, 256, 0, s2>>>(ei, batch);
    scanA_kernel<<<nscan, 1024, 0, s2>>>();
    scanC_kernel<<<nscan, 1024, 0, s2>>>(nscan);
    csr_kernel<<<(N_EDGES / 4 + 255) / 256, 256, 0, s2>>>(ei);
    cudaEventRecord(evJoin, s2);

    // default stream: conversions then layer-1 GEMM (independent of CSR)
    conv_kernel<<<(N_NODES * HID / 4 + 255) / 256, 256>>>(x, W1l, W1r, W2l, W2r, W3l, W3r);
    gemm_tc_kernel<<<ntiles, 256, SM_TOT>>>(xb, whi, wlo);

    // ---- join before first combine (needs CSR + inv_deg) ----
    cudaStreamWaitEvent(0, evJoin, 0);

    combine_kernel<<<N_NODES / 8, 256>>>(b1, hb0, nullptr, nullptr, 0);
    // layer 2
    gemm_tc_kernel<<<ntiles, 256, SM_TOT>>>(hb0, whi + 256 * 128, wlo + 256 * 128);
    combine_kernel<<<N_NODES / 8, 256>>>(b2, hb1, nullptr, nullptr, 0);
    // layer 3 (pool fused)
    gemm_tc_kernel<<<ntiles, 256, SM_TOT>>>(hb1, whi + 2 * 256 * 128, wlo + 2 * 256 * 128);
    combine_kernel<<<N_NODES / 8, 256>>>(b3, nullptr, batch, pooled, 1);

    div_kernel<<<(N_GRAPHS * HID + 255) / 256, 256>>>(pooled);
}

// round 16
// speedup vs baseline: 1.7436x; 1.0495x over previous
#include <cuda_runtime.h>
#include <cuda_bf16.h>
#include <cuda_fp16.h>
#include <cstdint>

#define N_NODES  50000
#define N_EDGES  800000
#define HID      128
#define N_GRAPHS 512
#define NTILES   ((N_NODES + 127) / 128)   // 391
#define GEMM_GRID 148

// ---------------- scratch ----------------
__device__ int   g_deg[N_NODES];
__device__ int   g_tmp_incl[N_NODES];
__device__ int   g_bsum[64];
__device__ int   g_cursor[N_NODES];
__device__ int   g_row_start[N_NODES + 1];
__device__ int   g_counts[N_GRAPHS];
__device__ int   g_csr_src[N_EDGES];
__device__ float g_inv_deg[N_NODES];

__device__ __half g_ylh[(size_t)N_NODES * 128];   // left-branch product, fp16 (gathered)
__device__ float  g_yr[(size_t)N_NODES * 128];    // right-branch product, fp32 (own row)

// single-bf16 activation buffers (weights keep hi/lo split; activations are bf16)
__device__ __nv_bfloat16 g_xb[(size_t)N_NODES * HID];
__device__ __nv_bfloat16 g_hb0[(size_t)N_NODES * HID];
__device__ __nv_bfloat16 g_hb1[(size_t)N_NODES * HID];
// converted weights: [layer][256 rows (Wl then Wr)][128 k]
__device__ __nv_bfloat16 g_whi[3 * 256 * 128];
__device__ __nv_bfloat16 g_wlo[3 * 256 * 128];

// ---------------- init: zero deg/counts/pooled ----------------
__global__ void init_kernel(float* __restrict__ pooled) {
    int i = blockIdx.x * blockDim.x + threadIdx.x;
    int stride = gridDim.x * blockDim.x;
    for (int j = i; j < N_NODES; j += stride) g_deg[j] = 0;
    for (int j = i; j < N_GRAPHS; j += stride) g_counts[j] = 0;
    for (int j = i; j < N_GRAPHS * HID; j += stride) pooled[j] = 0.0f;
}

// ---------------- histograms: 4 edges/thread (int4) ----------------
__global__ void hist_kernel(const int* __restrict__ ei, const int* __restrict__ batch) {
    int q = blockIdx.x * blockDim.x + threadIdx.x;
    if (q < N_EDGES / 4) {
        int4 d = *reinterpret_cast<const int4*>(&ei[N_EDGES + q * 4]);
        atomicAdd(&g_deg[d.x], 1);
        atomicAdd(&g_deg[d.y], 1);
        atomicAdd(&g_deg[d.z], 1);
        atomicAdd(&g_deg[d.w], 1);
    }
    if (q < N_NODES / 4) {
        int4 b = *reinterpret_cast<const int4*>(&batch[q * 4]);
        atomicAdd(&g_counts[b.x], 1);
        atomicAdd(&g_counts[b.y], 1);
        atomicAdd(&g_counts[b.z], 1);
        atomicAdd(&g_counts[b.w], 1);
    }
}

// ---------------- scan A: per-block inclusive scans of deg ----------------
__global__ __launch_bounds__(1024)
void scanA_kernel() {
    __shared__ int wsum[32];
    const int t = threadIdx.x, lane = t & 31, wid = t >> 5;
    const int i = blockIdx.x * 1024 + t;
    int v = (i < N_NODES) ? g_deg[i] : 0;
    int x = v;
#pragma unroll
    for (int o = 1; o < 32; o <<= 1) {
        int y = __shfl_up_sync(0xffffffffu, x, o);
        if (lane >= o) x += y;
    }
    if (lane == 31) wsum[wid] = x;
    __syncthreads();
    if (wid == 0) {
        int w = wsum[lane];
#pragma unroll
        for (int o = 1; o < 32; o <<= 1) {
            int y = __shfl_up_sync(0xffffffffu, w, o);
            if (lane >= o) w += y;
        }
        wsum[lane] = w;
    }
    __syncthreads();
    int incl = x + (wid ? wsum[wid - 1] : 0);
    if (i < N_NODES) g_tmp_incl[i] = incl;
    if (t == 1023) g_bsum[blockIdx.x] = incl;
}

// ---------------- scan C: redundant 64-wide block-sum scan + finalize ----------------
__global__ __launch_bounds__(1024)
void scanC_kernel(int nblocks) {
    __shared__ int s[64];
    const int t = threadIdx.x;
    if (t < 64) s[t] = (t < nblocks) ? g_bsum[t] : 0;
    __syncthreads();
#pragma unroll
    for (int o = 1; o < 64; o <<= 1) {
        int v = 0;
        if (t < 64 && t >= o) v = s[t - o];
        __syncthreads();
        if (t < 64) s[t] += v;
        __syncthreads();
    }
    const int i = blockIdx.x * 1024 + t;
    if (i >= N_NODES) return;
    int boff = blockIdx.x ? s[blockIdx.x - 1] : 0;
    int d = g_deg[i];
    int rs = boff + g_tmp_incl[i] - d;
    g_row_start[i] = rs;
    g_cursor[i]    = rs;
    g_inv_deg[i]   = 1.0f / fmaxf((float)d, 1.0f);
    if (i == N_NODES - 1) g_row_start[N_NODES] = rs + d;
}

// ---------------- CSR fill: 4 edges/thread (int4) ----------------
__global__ void csr_kernel(const int* __restrict__ ei) {
    int q = blockIdx.x * blockDim.x + threadIdx.x;
    if (q >= N_EDGES / 4) return;
    int4 s = *reinterpret_cast<const int4*>(&ei[q * 4]);
    int4 d = *reinterpret_cast<const int4*>(&ei[N_EDGES + q * 4]);
    int p0 = atomicAdd(&g_cursor[d.x], 1);
    int p1 = atomicAdd(&g_cursor[d.y], 1);
    int p2 = atomicAdd(&g_cursor[d.z], 1);
    int p3 = atomicAdd(&g_cursor[d.w], 1);
    g_csr_src[p0] = s.x;
    g_csr_src[p1] = s.y;
    g_csr_src[p2] = s.z;
    g_csr_src[p3] = s.w;
}

// ---------------- split helpers ----------------
__device__ __forceinline__ void split1(float v, __nv_bfloat16& hi, __nv_bfloat16& lo) {
    hi = __float2bfloat16_rn(v);
    lo = __float2bfloat16_rn(v - __bfloat162float(hi));
}
__device__ __forceinline__ uint32_t pack_bf2(float a, float b) {
    return ((uint32_t)__bfloat16_as_ushort(__float2bfloat16_rn(b)) << 16) |
           __bfloat16_as_ushort(__float2bfloat16_rn(a));
}

// ---------------- convert x (bf16 single) and weights (bf16 hi/lo) ----------------
__global__ void conv_kernel(const float* __restrict__ x,
                            const float* __restrict__ W1l, const float* __restrict__ W1r,
                            const float* __restrict__ W2l, const float* __restrict__ W2r,
                            const float* __restrict__ W3l, const float* __restrict__ W3r) {
    int i = blockIdx.x * blockDim.x + threadIdx.x;   // one float4 of x per thread
    if (i < N_NODES * HID / 4) {
        float4 v = *reinterpret_cast<const float4*>(&x[(size_t)i * 4]);
        uint2 u;
        u.x = pack_bf2(v.x, v.y);
        u.y = pack_bf2(v.z, v.w);
        *reinterpret_cast<uint2*>(&g_xb[(size_t)i * 4]) = u;
    }
    if (i < 3 * 256 * 128) {
        int layer = i / (256 * 128);
        int rem = i % (256 * 128);
        int n = rem / 128, k = rem % 128;
        const float* Wp;
        if (layer == 0) Wp = (n < 128) ? W1l : W1r;
        else if (layer == 1) Wp = (n < 128) ? W2l : W2r;
        else Wp = (n < 128) ? W3l : W3r;
        float v = Wp[(n & 127) * 128 + k];
        __nv_bfloat16 hi, lo;
        split1(v, hi, lo);
        g_whi[i] = hi;
        g_wlo[i] = lo;
    }
}

// ---------------- persistent mma.sync bf16 GEMM ----------------
// weight-only split: D = A@Bhi + A@Blo (fp32 accum); activations single bf16
// B staged ONCE per CTA; row-tiles looped with stride gridDim.
#define ASTR 136                       // smem row stride in bf16 elems (conflict-free)
static const int SM_A   = 0;
static const int SM_BHI = SM_A + 128 * ASTR * 2;     // 34816
static const int SM_BLO = SM_BHI + 256 * ASTR * 2;   // 104448
static const int SM_TOT = SM_BLO + 256 * ASTR * 2;   // 174080

__device__ __forceinline__ void mma16816(float* c, const uint32_t* a, const uint32_t* b) {
    asm volatile(
        "mma.sync.aligned.m16n8k16.row.col.f32.bf16.bf16.f32 "
        "{%0,%1,%2,%3}, {%4,%5,%6,%7}, {%8,%9}, {%0,%1,%2,%3};"
        : "+f"(c[0]), "+f"(c[1]), "+f"(c[2]), "+f"(c[3])
        : "r"(a[0]), "r"(a[1]), "r"(a[2]), "r"(a[3]), "r"(b[0]), "r"(b[1]));
}

__global__ __launch_bounds__(256, 1)
void gemm_tc_kernel(const __nv_bfloat16* __restrict__ Ab,
                    const __nv_bfloat16* __restrict__ Whi, const __nv_bfloat16* __restrict__ Wlo) {
    extern __shared__ char smem[];
    const int t = threadIdx.x;

    // ---- stage B ONCE (256x128 bf16 hi/lo) ----
#pragma unroll
    for (int i = t; i < 256 * 16; i += 256) {
        int n = i >> 4, k = (i & 15) * 8;
        *reinterpret_cast<uint4*>(smem + SM_BHI + (n * ASTR + k) * 2) =
            *reinterpret_cast<const uint4*>(&Whi[n * HID + k]);
        *reinterpret_cast<uint4*>(smem + SM_BLO + (n * ASTR + k) * 2) =
            *reinterpret_cast<const uint4*>(&Wlo[n * HID + k]);
    }

    const int wid = t >> 5, lane = t & 31;
    const int g = lane >> 2, tig = lane & 3;
    const int wm = (wid & 1) * 64;        // warp M offset (2 warps in M)
    const int wn = (wid >> 1) * 64;       // warp N offset (4 warps in N)

    for (int tile = blockIdx.x; tile < NTILES; tile += GEMM_GRID) {
        const int row0 = tile * 128;

        // ---- stage A (128x128 bf16) ----
#pragma unroll
        for (int i = t; i < 128 * 16; i += 256) {
            int r = i >> 4, k = (i & 15) * 8;
            int row = row0 + r;
            uint4 va = make_uint4(0, 0, 0, 0);
            if (row < N_NODES)
                va = *reinterpret_cast<const uint4*>(&Ab[(size_t)row * HID + k]);
            *reinterpret_cast<uint4*>(smem + SM_A + (r * ASTR + k) * 2) = va;
        }
        __syncthreads();   // A (and on iter 0, B) visible to all warps

        float acc[4][8][4];
#pragma unroll
        for (int a = 0; a < 4; a++)
#pragma unroll
            for (int b = 0; b < 8; b++)
#pragma unroll
                for (int c = 0; c < 4; c++) acc[a][b][c] = 0.0f;

        for (int ks = 0; ks < 8; ks++) {
            const int k0 = ks * 16 + tig * 2;
            uint32_t ah[4][4];
#pragma unroll
            for (int mt = 0; mt < 4; mt++) {
                int base = ((wm + mt * 16 + g) * ASTR + k0) * 2;
                ah[mt][0] = *reinterpret_cast<const uint32_t*>(smem + SM_A + base);
                ah[mt][1] = *reinterpret_cast<const uint32_t*>(smem + SM_A + base + 8 * ASTR * 2);
                ah[mt][2] = *reinterpret_cast<const uint32_t*>(smem + SM_A + base + 16);
                ah[mt][3] = *reinterpret_cast<const uint32_t*>(smem + SM_A + base + 8 * ASTR * 2 + 16);
            }
#pragma unroll
            for (int nh = 0; nh < 2; nh++) {
                uint32_t bh[4][2], bl[4][2];
#pragma unroll
                for (int nt = 0; nt < 4; nt++) {
                    int base = ((wn + nh * 32 + nt * 8 + g) * ASTR + k0) * 2;
                    bh[nt][0] = *reinterpret_cast<const uint32_t*>(smem + SM_BHI + base);
                    bh[nt][1] = *reinterpret_cast<const uint32_t*>(smem + SM_BHI + base + 16);
                    bl[nt][0] = *reinterpret_cast<const uint32_t*>(smem + SM_BLO + base);
                    bl[nt][1] = *reinterpret_cast<const uint32_t*>(smem + SM_BLO + base + 16);
                }
#pragma unroll
                for (int mt = 0; mt < 4; mt++)
#pragma unroll
                    for (int nt = 0; nt < 4; nt++) {
                        float* c = acc[mt][nh * 4 + nt];
                        mma16816(c, ah[mt], bh[nt]);
                        mma16816(c, ah[mt], bl[nt]);
                    }
            }
        }

        // ---- epilogue: cols [0,128) -> fp16 g_ylh ; cols [128,256) -> fp32 g_yr ----
#pragma unroll
        for (int mt = 0; mt < 4; mt++)
#pragma unroll
            for (int nt = 0; nt < 8; nt++) {
                int row = row0 + wm + mt * 16 + g;
                int col = wn + nt * 8 + tig * 2;
                float* c = acc[mt][nt];
                if (col < 128) {
                    if (row < N_NODES)
                        *reinterpret_cast<__half2*>(&g_ylh[(size_t)row * 128 + col]) =
                            __floats2half2_rn(c[0], c[1]);
                    if (row + 8 < N_NODES)
                        *reinterpret_cast<__half2*>(&g_ylh[(size_t)(row + 8) * 128 + col]) =
                            __floats2half2_rn(c[2], c[3]);
                } else {
                    int cr = col - 128;
                    if (row < N_NODES)
                        *reinterpret_cast<float2*>(&g_yr[(size_t)row * 128 + cr]) = make_float2(c[0], c[1]);
                    if (row + 8 < N_NODES)
                        *reinterpret_cast<float2*>(&g_yr[(size_t)(row + 8) * 128 + cr]) = make_float2(c[2], c[3]);
                }
            }
        __syncthreads();   // all warps done reading A before next-iter overwrite
    }
}

// ---------------- combine: 32 lanes/node, 4-chain unroll, uint2 fp16 gathers ----------------
__device__ __forceinline__ void acc_half4(float4& acc, const __half* p) {
    uint2 u = *reinterpret_cast<const uint2*>(p);
    float2 f0 = __half22float2(*reinterpret_cast<__half2*>(&u.x));
    float2 f1 = __half22float2(*reinterpret_cast<__half2*>(&u.y));
    acc.x += f0.x; acc.y += f0.y; acc.z += f1.x; acc.w += f1.y;
}

__global__ __launch_bounds__(256)
void combine_kernel(const float* __restrict__ bias,
                    __nv_bfloat16* __restrict__ Hout,
                    const int* __restrict__ batch, float* __restrict__ pooled,
                    int do_pool) {
    int i = (blockIdx.x * blockDim.x + threadIdx.x) >> 5;
    if (i >= N_NODES) return;
    int lane = threadIdx.x & 31;
    int e0 = g_row_start[i], e1 = g_row_start[i + 1];
    float4 acc0 = make_float4(0, 0, 0, 0), acc1 = make_float4(0, 0, 0, 0);
    float4 acc2 = make_float4(0, 0, 0, 0), acc3 = make_float4(0, 0, 0, 0);
    int e = e0;
    const int lo4 = lane * 4;
    for (; e + 4 <= e1; e += 4) {
        int s0 = g_csr_src[e], s1 = g_csr_src[e + 1];
        int s2 = g_csr_src[e + 2], s3 = g_csr_src[e + 3];
        acc_half4(acc0, &g_ylh[(size_t)s0 * 128 + lo4]);
        acc_half4(acc1, &g_ylh[(size_t)s1 * 128 + lo4]);
        acc_half4(acc2, &g_ylh[(size_t)s2 * 128 + lo4]);
        acc_half4(acc3, &g_ylh[(size_t)s3 * 128 + lo4]);
    }
    for (; e < e1; e++) {
        int s0 = g_csr_src[e];
        acc_half4(acc0, &g_ylh[(size_t)s0 * 128 + lo4]);
    }
    acc0.x += acc1.x + acc2.x + acc3.x;
    acc0.y += acc1.y + acc2.y + acc3.y;
    acc0.z += acc1.z + acc2.z + acc3.z;
    acc0.w += acc1.w + acc2.w + acc3.w;

    float inv = g_inv_deg[i];
    float4 yr = *reinterpret_cast<const float4*>(&g_yr[(size_t)i * 128 + lo4]);
    float4 bb = *reinterpret_cast<const float4*>(&bias[lo4]);
    float4 r;
    r.x = fmaxf(fmaf(acc0.x, inv, yr.x + bb.x), 0.0f);
    r.y = fmaxf(fmaf(acc0.y, inv, yr.y + bb.y), 0.0f);
    r.z = fmaxf(fmaf(acc0.z, inv, yr.z + bb.z), 0.0f);
    r.w = fmaxf(fmaf(acc0.w, inv, yr.w + bb.w), 0.0f);
    if (!do_pool) {
        uint2 u;
        u.x = pack_bf2(r.x, r.y);
        u.y = pack_bf2(r.z, r.w);
        *reinterpret_cast<uint2*>(&Hout[(size_t)i * HID + lo4]) = u;
    } else {
        int g = batch[i];
        float* p = &pooled[(size_t)g * HID + lo4];
        atomicAdd(p + 0, r.x);
        atomicAdd(p + 1, r.y);
        atomicAdd(p + 2, r.z);
        atomicAdd(p + 3, r.w);
    }
}

// ---------------- final divide ----------------
__global__ void div_kernel(float* __restrict__ pooled) {
    int idx = blockIdx.x * blockDim.x + threadIdx.x;
    if (idx < N_GRAPHS * HID) {
        int g = idx >> 7;
        pooled[idx] *= 1.0f / fmaxf((float)g_counts[g], 1.0f);
    }
}

// ---------------- launch ----------------
extern "C" void kernel_launch(void* const* d_in, const int* in_sizes, int n_in,
                              void* d_out, int out_size) {
    const float* x     = (const float*)d_in[0];
    const int*   ei    = (const int*)d_in[1];
    const int*   batch = (const int*)d_in[2];
    const float* W1l = (const float*)d_in[3];
    const float* W1r = (const float*)d_in[4];
    const float* b1  = (const float*)d_in[5];
    const float* W2l = (const float*)d_in[6];
    const float* W2r = (const float*)d_in[7];
    const float* b2  = (const float*)d_in[8];
    const float* W3l = (const float*)d_in[9];
    const float* W3r = (const float*)d_in[10];
    const float* b3  = (const float*)d_in[11];
    float* pooled = (float*)d_out;

    __nv_bfloat16 *xb, *hb0, *hb1, *whi, *wlo;
    cudaGetSymbolAddress((void**)&xb,  g_xb);
    cudaGetSymbolAddress((void**)&hb0, g_hb0);
    cudaGetSymbolAddress((void**)&hb1, g_hb1);
    cudaGetSymbolAddress((void**)&whi, g_whi);
    cudaGetSymbolAddress((void**)&wlo, g_wlo);

    cudaFuncSetAttribute(gemm_tc_kernel, cudaFuncAttributeMaxDynamicSharedMemorySize, SM_TOT);

    // lazy one-time stream/event creation (first call is the uncaptured correctness run)
    static cudaStream_t s2 = nullptr;
    static cudaEvent_t evFork = nullptr, evJoin = nullptr;
    if (!s2) {
        cudaStreamCreateWithFlags(&s2, cudaStreamNonBlocking);
        cudaEventCreateWithFlags(&evFork, cudaEventDisableTiming);
        cudaEventCreateWithFlags(&evJoin, cudaEventDisableTiming);
    }

    const int nscan = (N_NODES + 1023) / 1024;   // 49

    // ---- fork: graph-setup chain on s2, concurrent with conv+gemm1 on default ----
    cudaEventRecord(evFork, 0);
    cudaStreamWaitEvent(s2, evFork, 0);

    init_kernel<<<256, 256, 0, s2>>>(pooled);
    hist_kernel<<<(N_EDGES / 4 + 255) / 256, 256, 0, s2>>>(ei, batch);
    scanA_kernel<<<nscan, 1024, 0, s2>>>();
    scanC_kernel<<<nscan, 1024, 0, s2>>>(nscan);
    csr_kernel<<<(N_EDGES / 4 + 255) / 256, 256, 0, s2>>>(ei);
    cudaEventRecord(evJoin, s2);

    // default stream: conversions then layer-1 GEMM (independent of CSR)
    conv_kernel<<<(N_NODES * HID / 4 + 255) / 256, 256>>>(x, W1l, W1r, W2l, W2r, W3l, W3r);
    gemm_tc_kernel<<<GEMM_GRID, 256, SM_TOT>>>(xb, whi, wlo);

    // ---- join before first combine (needs CSR + inv_deg) ----
    cudaStreamWaitEvent(0, evJoin, 0);

    combine_kernel<<<N_NODES / 8, 256>>>(b1, hb0, nullptr, nullptr, 0);
    // layer 2
    gemm_tc_kernel<<<GEMM_GRID, 256, SM_TOT>>>(hb0, whi + 256 * 128, wlo + 256 * 128);
    combine_kernel<<<N_NODES / 8, 256>>>(b2, hb1, nullptr, nullptr, 0);
    // layer 3 (pool fused)
    gemm_tc_kernel<<<GEMM_GRID, 256, SM_TOT>>>(hb1, whi + 2 * 256 * 128, wlo + 2 * 256 * 128);
    combine_kernel<<<N_NODES / 8, 256>>>(b3, nullptr, batch, pooled, 1);

    div_kernel<<<(N_GRAPHS * HID + 255) / 256, 256>>>(pooled);
}